// round 1
// baseline (speedup 1.0000x reference)
#include <cuda_runtime.h>

#define N_NODES 8192
#define IN_FEAT 128
#define OUT_FEAT 64
#define E_EDGES 131072
#define C2 128   // concat width of [w_mu | w_ls] output

// ---------------- device scratch (no allocation allowed) ----------------
__device__ int    g_deg[N_NODES];
__device__ int    g_off[N_NODES + 1];
__device__ int    g_cursor[N_NODES];
__device__ int    g_perm[E_EDGES];
__device__ float  g_norm[N_NODES];
__device__ float  g_X0[N_NODES * OUT_FEAT];    // (h*norm)@w0
__device__ float  g_h1n[N_NODES * OUT_FEAT];   // relu(agg*norm)*norm
__device__ float  g_Y[N_NODES * C2];           // h1n @ [w_mu | w_ls]
__device__ float  g_z[N_NODES * OUT_FEAT];
__device__ double g_edge_sum;
__device__ double g_sp_sum;

// ---------------- init ----------------
__global__ void k_zero() {
    int i = blockIdx.x * blockDim.x + threadIdx.x;
    if (i < N_NODES) g_deg[i] = 0;
    if (i == 0) { g_edge_sum = 0.0; g_sp_sum = 0.0; }
}

__global__ void k_deg(const int* __restrict__ src) {
    int e = blockIdx.x * blockDim.x + threadIdx.x;
    if (e < E_EDGES) atomicAdd(&g_deg[src[e]], 1);
}

// single-block exclusive scan of deg -> offsets; also norm + cursor init
__global__ void k_scan_norm() {
    __shared__ int part[1024];
    int tid = threadIdx.x;          // blockDim = 1024, 8 elems/thread
    int base = tid * 8;
    int local[8];
    int s = 0;
    #pragma unroll
    for (int j = 0; j < 8; j++) { local[j] = s; s += g_deg[base + j]; }
    part[tid] = s;
    __syncthreads();
    for (int off = 1; off < 1024; off <<= 1) {
        int v = (tid >= off) ? part[tid - off] : 0;
        __syncthreads();
        part[tid] += v;
        __syncthreads();
    }
    int pre = (tid > 0) ? part[tid - 1] : 0;
    #pragma unroll
    for (int j = 0; j < 8; j++) {
        int o = pre + local[j];
        g_off[base + j] = o;
        g_cursor[base + j] = o;
        int d = g_deg[base + j];
        g_norm[base + j] = rsqrtf((float)(d < 1 ? 1 : d));
    }
    if (tid == 1023) g_off[N_NODES] = pre + s;
}

__global__ void k_perm(const int* __restrict__ src, const int* __restrict__ dst) {
    int e = blockIdx.x * blockDim.x + threadIdx.x;
    if (e < E_EDGES) {
        int p = atomicAdd(&g_cursor[src[e]], 1);
        g_perm[p] = dst[e];
    }
}

// ---------------- GEMM 1: X0 = (h * norm) @ w0   [8192x128 @ 128x64] ----------------
__global__ void __launch_bounds__(512) k_gemm1(const float* __restrict__ h,
                                               const float* __restrict__ w0) {
    __shared__ float ws[IN_FEAT][OUT_FEAT];  // 32 KB
    __shared__ float hs[8][IN_FEAT];         // 4 KB
    int tid = threadIdx.x;                   // 512
    int row0 = blockIdx.x * 8;
    for (int t = tid; t < IN_FEAT * OUT_FEAT; t += 512)
        ws[t >> 6][t & 63] = w0[t];
    for (int t = tid; t < 8 * IN_FEAT; t += 512) {
        int r = t >> 7, k = t & 127;
        hs[r][k] = h[(row0 + r) * IN_FEAT + k] * g_norm[row0 + r];
    }
    __syncthreads();
    int r = tid >> 6, c = tid & 63;
    float acc = 0.f;
    #pragma unroll
    for (int k = 0; k < IN_FEAT; k++) acc = fmaf(hs[r][k], ws[k][c], acc);
    g_X0[(row0 + r) * OUT_FEAT + c] = acc;
}

// ---------------- gather 1: h1n = relu(sum X0[dst] * norm) * norm ----------------
__global__ void k_gather1() {
    int w = (blockIdx.x * blockDim.x + threadIdx.x) >> 5;
    int lane = threadIdx.x & 31;
    if (w >= N_NODES) return;
    int beg = g_off[w], end = g_off[w + 1];
    float a0 = 0.f, a1 = 0.f;
    for (int e = beg; e < end; e++) {
        int d = g_perm[e];
        const float* xr = &g_X0[d * OUT_FEAT];
        a0 += xr[lane];
        a1 += xr[lane + 32];
    }
    float nm = g_norm[w];
    g_h1n[w * OUT_FEAT + lane]      = fmaxf(a0 * nm, 0.f) * nm;
    g_h1n[w * OUT_FEAT + lane + 32] = fmaxf(a1 * nm, 0.f) * nm;
}

// ---------------- GEMM 2: Y = h1n @ [w_mu | w_ls]   [8192x64 @ 64x128] ----------------
__global__ void __launch_bounds__(1024) k_gemm2(const float* __restrict__ wmu,
                                                const float* __restrict__ wls) {
    __shared__ float ws[OUT_FEAT][C2];  // 32 KB
    __shared__ float hs[8][OUT_FEAT];   // 2 KB
    int tid = threadIdx.x;              // 1024
    int row0 = blockIdx.x * 8;
    for (int t = tid; t < OUT_FEAT * OUT_FEAT; t += 1024) {
        int k = t >> 6, c = t & 63;
        ws[k][c]      = wmu[t];
        ws[k][c + 64] = wls[t];
    }
    for (int t = tid; t < 8 * OUT_FEAT; t += 1024) {
        int r = t >> 6, k = t & 63;
        hs[r][k] = g_h1n[(row0 + r) * OUT_FEAT + k];
    }
    __syncthreads();
    int r = tid >> 7, c = tid & 127;
    float acc = 0.f;
    #pragma unroll
    for (int k = 0; k < OUT_FEAT; k++) acc = fmaf(hs[r][k], ws[k][c], acc);
    g_Y[(row0 + r) * C2 + c] = acc;
}

// ---------------- gather 2 + reparam + KL (KL -> out) ----------------
__global__ void k_gather2(const float* __restrict__ eps, float* __restrict__ out) {
    int w = (blockIdx.x * blockDim.x + threadIdx.x) >> 5;
    int lane = threadIdx.x & 31;
    if (w >= N_NODES) return;
    int beg = g_off[w], end = g_off[w + 1];
    float m0 = 0.f, m1 = 0.f, l0 = 0.f, l1 = 0.f;
    for (int e = beg; e < end; e++) {
        int d = g_perm[e];
        const float* yr = &g_Y[d * C2];
        m0 += yr[lane];      m1 += yr[lane + 32];
        l0 += yr[lane + 64]; l1 += yr[lane + 96];
    }
    float nm = g_norm[w];
    m0 *= nm; m1 *= nm; l0 *= nm; l1 *= nm;
    float s0 = __expf(l0), s1 = __expf(l1);
    float z0 = m0 + s0 * eps[w * OUT_FEAT + lane];
    float z1 = m1 + s1 * eps[w * OUT_FEAT + lane + 32];
    g_z[w * OUT_FEAT + lane]      = z0;
    g_z[w * OUT_FEAT + lane + 32] = z1;
    out[w * OUT_FEAT + lane]      = -l0 + 0.5f * (s0 * s0 + m0 * m0 - 1.f);
    out[w * OUT_FEAT + lane + 32] = -l1 + 0.5f * (s1 * s1 + m1 * m1 - 1.f);
}

// ---------------- edge term: sum_e z[src].z[dst]  (with multiplicity) ----------------
__global__ void k_edge(const int* __restrict__ src, const int* __restrict__ dst) {
    int gw = (blockIdx.x * blockDim.x + threadIdx.x) >> 5;
    int lane = threadIdx.x & 31;
    int nwarps = (gridDim.x * blockDim.x) >> 5;
    float acc = 0.f;
    for (int e = gw; e < E_EDGES; e += nwarps) {
        int s = src[e], d = dst[e];
        acc += g_z[s * OUT_FEAT + lane] * g_z[d * OUT_FEAT + lane]
             + g_z[s * OUT_FEAT + lane + 32] * g_z[d * OUT_FEAT + lane + 32];
    }
    #pragma unroll
    for (int o = 16; o; o >>= 1) acc += __shfl_xor_sync(0xffffffffu, acc, o);
    __shared__ float red[8];
    if (lane == 0) red[threadIdx.x >> 5] = acc;
    __syncthreads();
    if (threadIdx.x == 0) {
        float s = 0.f;
        #pragma unroll
        for (int i = 0; i < 8; i++) s += red[i];
        atomicAdd(&g_edge_sum, (double)s);
    }
}

// ---------------- dominant kernel: sum_ij softplus(z_i . z_j), symmetric tiles ----------------
// 64x64 CTA tile, 4x4 micro-tile, k-major smem (padded 68) for float4 LDS.
__global__ void __launch_bounds__(256) k_softplus() {
    int ti = blockIdx.y, tj = blockIdx.x;
    if (tj < ti) return;                 // upper triangle only (symmetry)
    __shared__ float Zi[64][68];
    __shared__ float Zj[64][68];
    int tid = threadIdx.x;               // 256
    const float* zi = g_z + ti * 64 * OUT_FEAT;  // tile rows are contiguous
    const float* zj = g_z + tj * 64 * OUT_FEAT;
    for (int t = tid; t < 4096; t += 256) {
        int r = t >> 6, k = t & 63;
        Zi[k][r] = zi[t];
        Zj[k][r] = zj[t];
    }
    __syncthreads();

    int tx = tid & 15, ty = tid >> 4;
    float acc[4][4];
    #pragma unroll
    for (int r = 0; r < 4; r++)
        #pragma unroll
        for (int c = 0; c < 4; c++) acc[r][c] = 0.f;

    #pragma unroll 4
    for (int k = 0; k < 64; k++) {
        float4 av = *(const float4*)&Zi[k][ty * 4];
        float4 bv = *(const float4*)&Zj[k][tx * 4];
        float a0 = av.x, a1 = av.y, a2 = av.z, a3 = av.w;
        float b0 = bv.x, b1 = bv.y, b2 = bv.z, b3 = bv.w;
        acc[0][0] = fmaf(a0, b0, acc[0][0]); acc[0][1] = fmaf(a0, b1, acc[0][1]);
        acc[0][2] = fmaf(a0, b2, acc[0][2]); acc[0][3] = fmaf(a0, b3, acc[0][3]);
        acc[1][0] = fmaf(a1, b0, acc[1][0]); acc[1][1] = fmaf(a1, b1, acc[1][1]);
        acc[1][2] = fmaf(a1, b2, acc[1][2]); acc[1][3] = fmaf(a1, b3, acc[1][3]);
        acc[2][0] = fmaf(a2, b0, acc[2][0]); acc[2][1] = fmaf(a2, b1, acc[2][1]);
        acc[2][2] = fmaf(a2, b2, acc[2][2]); acc[2][3] = fmaf(a2, b3, acc[2][3]);
        acc[3][0] = fmaf(a3, b0, acc[3][0]); acc[3][1] = fmaf(a3, b1, acc[3][1]);
        acc[3][2] = fmaf(a3, b2, acc[3][2]); acc[3][3] = fmaf(a3, b3, acc[3][3]);
    }

    float s = 0.f;
    #pragma unroll
    for (int r = 0; r < 4; r++)
        #pragma unroll
        for (int c = 0; c < 4; c++) {
            float x = acc[r][c];
            // softplus(x) = max(x,0) + log(1 + exp(-|x|))
            s += fmaxf(x, 0.f) + __logf(1.f + __expf(-fabsf(x)));
        }

    __shared__ float red[256];
    red[tid] = s;
    __syncthreads();
    #pragma unroll
    for (int o = 128; o; o >>= 1) {
        if (tid < o) red[tid] += red[tid + o];
        __syncthreads();
    }
    if (tid == 0) {
        double w = (ti == tj) ? 1.0 : 2.0;   // off-diagonal tiles count twice
        atomicAdd(&g_sp_sum, w * (double)red[0]);
    }
}

// ---------------- finalize: out = kl - recon ----------------
__global__ void k_finalize(float* __restrict__ out) {
    int i = blockIdx.x * blockDim.x + threadIdx.x;
    float recon = (float)((g_edge_sum - g_sp_sum) / (double)N_NODES);
    if (i < N_NODES * OUT_FEAT) out[i] -= recon;
}

// ---------------- launch ----------------
extern "C" void kernel_launch(void* const* d_in, const int* in_sizes, int n_in,
                              void* d_out, int out_size) {
    const float* h   = (const float*)d_in[0];
    const int*   src = (const int*)d_in[1];
    const int*   dst = (const int*)d_in[2];
    const float* eps = (const float*)d_in[3];
    const float* w0  = (const float*)d_in[4];
    const float* wmu = (const float*)d_in[5];
    const float* wls = (const float*)d_in[6];
    float* out = (float*)d_out;

    k_zero<<<(N_NODES + 255) / 256, 256>>>();
    k_deg<<<E_EDGES / 256, 256>>>(src);
    k_scan_norm<<<1, 1024>>>();
    k_perm<<<E_EDGES / 256, 256>>>(src, dst);
    k_gemm1<<<N_NODES / 8, 512>>>(h, w0);
    k_gather1<<<N_NODES / 8, 256>>>();
    k_gemm2<<<N_NODES / 8, 1024>>>(wmu, wls);
    k_gather2<<<N_NODES / 8, 256>>>(eps, out);
    k_edge<<<256, 256>>>(src, dst);
    dim3 grid_sp(128, 128);
    k_softplus<<<grid_sp, 256>>>();
    k_finalize<<<(N_NODES * OUT_FEAT) / 256, 256>>>(out);
}

// round 3
// speedup vs baseline: 1.5659x; 1.5659x over previous
#include <cuda_runtime.h>
#include <cuda_bf16.h>
#include <cstdint>

#define N_NODES 8192
#define IN_FEAT 128
#define OUT_FEAT 64
#define E_EDGES 131072
#define C2 128

// ---------------- device scratch ----------------
__device__ int    g_deg[N_NODES];
__device__ int    g_off[N_NODES + 1];
__device__ int    g_cursor[N_NODES];
__device__ int    g_perm[E_EDGES];
__device__ float  g_norm[N_NODES];
__device__ float  g_X0[N_NODES * OUT_FEAT];
__device__ float  g_h1n[N_NODES * OUT_FEAT];
__device__ float  g_Y[N_NODES * C2];
__device__ float  g_z[N_NODES * OUT_FEAT];
__device__ __nv_bfloat16 g_ZA[N_NODES * 192];   // [hi | hi | lo]
__device__ __nv_bfloat16 g_ZB[N_NODES * 192];   // [hi | lo | hi]
__device__ double g_edge_sum;
__device__ double g_sp_sum;

// ---------------- init / graph prep ----------------
__global__ void k_zero() {
    int i = blockIdx.x * blockDim.x + threadIdx.x;
    if (i < N_NODES) g_deg[i] = 0;
    if (i == 0) { g_edge_sum = 0.0; g_sp_sum = 0.0; }
}
__global__ void k_deg(const int* __restrict__ src) {
    int e = blockIdx.x * blockDim.x + threadIdx.x;
    if (e < E_EDGES) atomicAdd(&g_deg[src[e]], 1);
}
__global__ void k_scan_norm() {
    __shared__ int part[1024];
    int tid = threadIdx.x;
    int base = tid * 8;
    int local[8];
    int s = 0;
    #pragma unroll
    for (int j = 0; j < 8; j++) { local[j] = s; s += g_deg[base + j]; }
    part[tid] = s;
    __syncthreads();
    for (int off = 1; off < 1024; off <<= 1) {
        int v = (tid >= off) ? part[tid - off] : 0;
        __syncthreads();
        part[tid] += v;
        __syncthreads();
    }
    int pre = (tid > 0) ? part[tid - 1] : 0;
    #pragma unroll
    for (int j = 0; j < 8; j++) {
        int o = pre + local[j];
        g_off[base + j] = o;
        g_cursor[base + j] = o;
        int d = g_deg[base + j];
        g_norm[base + j] = rsqrtf((float)(d < 1 ? 1 : d));
    }
    if (tid == 1023) g_off[N_NODES] = pre + s;
}
__global__ void k_perm(const int* __restrict__ src, const int* __restrict__ dst) {
    int e = blockIdx.x * blockDim.x + threadIdx.x;
    if (e < E_EDGES) {
        int p = atomicAdd(&g_cursor[src[e]], 1);
        g_perm[p] = dst[e];
    }
}

// ---------------- GEMM 1: X0 = (h * norm) @ w0 ----------------
__global__ void __launch_bounds__(512) k_gemm1(const float* __restrict__ h,
                                               const float* __restrict__ w0) {
    __shared__ float ws[IN_FEAT][OUT_FEAT];
    __shared__ float hs[8][IN_FEAT];
    int tid = threadIdx.x;
    int row0 = blockIdx.x * 8;
    for (int t = tid; t < IN_FEAT * OUT_FEAT; t += 512)
        ws[t >> 6][t & 63] = w0[t];
    for (int t = tid; t < 8 * IN_FEAT; t += 512) {
        int r = t >> 7, k = t & 127;
        hs[r][k] = h[(row0 + r) * IN_FEAT + k] * g_norm[row0 + r];
    }
    __syncthreads();
    int r = tid >> 6, c = tid & 63;
    float acc = 0.f;
    #pragma unroll
    for (int k = 0; k < IN_FEAT; k++) acc = fmaf(hs[r][k], ws[k][c], acc);
    g_X0[(row0 + r) * OUT_FEAT + c] = acc;
}

// ---------------- gather 1 ----------------
__global__ void k_gather1() {
    int w = (blockIdx.x * blockDim.x + threadIdx.x) >> 5;
    int lane = threadIdx.x & 31;
    if (w >= N_NODES) return;
    int beg = g_off[w], end = g_off[w + 1];
    float a0 = 0.f, a1 = 0.f;
    for (int e = beg; e < end; e++) {
        int d = g_perm[e];
        const float* xr = &g_X0[d * OUT_FEAT];
        a0 += xr[lane];
        a1 += xr[lane + 32];
    }
    float nm = g_norm[w];
    g_h1n[w * OUT_FEAT + lane]      = fmaxf(a0 * nm, 0.f) * nm;
    g_h1n[w * OUT_FEAT + lane + 32] = fmaxf(a1 * nm, 0.f) * nm;
}

// ---------------- GEMM 2: Y = h1n @ [w_mu | w_ls] ----------------
__global__ void __launch_bounds__(1024) k_gemm2(const float* __restrict__ wmu,
                                                const float* __restrict__ wls) {
    __shared__ float ws[OUT_FEAT][C2];
    __shared__ float hs[8][OUT_FEAT];
    int tid = threadIdx.x;
    int row0 = blockIdx.x * 8;
    for (int t = tid; t < OUT_FEAT * OUT_FEAT; t += 1024) {
        int k = t >> 6, c = t & 63;
        ws[k][c]      = wmu[t];
        ws[k][c + 64] = wls[t];
    }
    for (int t = tid; t < 8 * OUT_FEAT; t += 1024) {
        int r = t >> 6, k = t & 63;
        hs[r][k] = g_h1n[(row0 + r) * OUT_FEAT + k];
    }
    __syncthreads();
    int r = tid >> 7, c = tid & 127;
    float acc = 0.f;
    #pragma unroll
    for (int k = 0; k < OUT_FEAT; k++) acc = fmaf(hs[r][k], ws[k][c], acc);
    g_Y[(row0 + r) * C2 + c] = acc;
}

// ---------------- gather 2 + reparam + KL ----------------
__global__ void k_gather2(const float* __restrict__ eps, float* __restrict__ out) {
    int w = (blockIdx.x * blockDim.x + threadIdx.x) >> 5;
    int lane = threadIdx.x & 31;
    if (w >= N_NODES) return;
    int beg = g_off[w], end = g_off[w + 1];
    float m0 = 0.f, m1 = 0.f, l0 = 0.f, l1 = 0.f;
    for (int e = beg; e < end; e++) {
        int d = g_perm[e];
        const float* yr = &g_Y[d * C2];
        m0 += yr[lane];      m1 += yr[lane + 32];
        l0 += yr[lane + 64]; l1 += yr[lane + 96];
    }
    float nm = g_norm[w];
    m0 *= nm; m1 *= nm; l0 *= nm; l1 *= nm;
    float s0 = __expf(l0), s1 = __expf(l1);
    float z0 = m0 + s0 * eps[w * OUT_FEAT + lane];
    float z1 = m1 + s1 * eps[w * OUT_FEAT + lane + 32];
    g_z[w * OUT_FEAT + lane]      = z0;
    g_z[w * OUT_FEAT + lane + 32] = z1;
    out[w * OUT_FEAT + lane]      = -l0 + 0.5f * (s0 * s0 + m0 * m0 - 1.f);
    out[w * OUT_FEAT + lane + 32] = -l1 + 0.5f * (s1 * s1 + m1 * m1 - 1.f);
}

// ---------------- prep: split z into bf16 hi/lo, packed along K ----------------
__global__ void k_prep() {
    int i = blockIdx.x * blockDim.x + threadIdx.x;
    if (i >= N_NODES * OUT_FEAT) return;
    int n = i >> 6, d = i & 63;
    float z = g_z[i];
    __nv_bfloat16 hi = __float2bfloat16(z);
    __nv_bfloat16 lo = __float2bfloat16(z - __bfloat162float(hi));
    __nv_bfloat16* za = &g_ZA[n * 192];
    __nv_bfloat16* zb = &g_ZB[n * 192];
    za[d] = hi; za[64 + d] = hi; za[128 + d] = lo;
    zb[d] = hi; zb[64 + d] = lo; zb[128 + d] = hi;
}

// ---------------- edge term ----------------
__global__ void k_edge(const int* __restrict__ src, const int* __restrict__ dst) {
    int gw = (blockIdx.x * blockDim.x + threadIdx.x) >> 5;
    int lane = threadIdx.x & 31;
    int nwarps = (gridDim.x * blockDim.x) >> 5;
    float acc = 0.f;
    for (int e = gw; e < E_EDGES; e += nwarps) {
        int s = src[e], d = dst[e];
        acc += g_z[s * OUT_FEAT + lane] * g_z[d * OUT_FEAT + lane]
             + g_z[s * OUT_FEAT + lane + 32] * g_z[d * OUT_FEAT + lane + 32];
    }
    #pragma unroll
    for (int o = 16; o; o >>= 1) acc += __shfl_xor_sync(0xffffffffu, acc, o);
    __shared__ float red[8];
    if (lane == 0) red[threadIdx.x >> 5] = acc;
    __syncthreads();
    if (threadIdx.x == 0) {
        float s = 0.f;
        #pragma unroll
        for (int i = 0; i < 8; i++) s += red[i];
        atomicAdd(&g_edge_sum, (double)s);
    }
}

// ---------------- dominant kernel: HMMA tiles of softplus(z zT) ----------------
// mma.sync.m16n8k16 bf16, 128x128 CTA tile, K=192 split-bf16.
// Triangular tile schedule: 64*65/2 = 2080 CTAs, off-diagonal weight 2.
#define NTILES 2080
#define SROW 200   // smem stride in bf16 (100 words ≡ 4 mod 32 → conflict-free frags)
#define SP_SMEM (2 * 128 * SROW * 2 + 1024)

__device__ __forceinline__ void mma_bf16(float* c, const uint32_t* a, const uint32_t* b) {
    asm volatile(
        "mma.sync.aligned.m16n8k16.row.col.f32.bf16.bf16.f32 "
        "{%0,%1,%2,%3}, {%4,%5,%6,%7}, {%8,%9}, {%0,%1,%2,%3};"
        : "+f"(c[0]), "+f"(c[1]), "+f"(c[2]), "+f"(c[3])
        : "r"(a[0]), "r"(a[1]), "r"(a[2]), "r"(a[3]), "r"(b[0]), "r"(b[1]));
}

__global__ void __launch_bounds__(256) k_sp_mma() {
    extern __shared__ char smem[];
    __nv_bfloat16* As = (__nv_bfloat16*)smem;            // [128][SROW]
    __nv_bfloat16* Bs = As + 128 * SROW;
    float* red = (float*)(Bs + 128 * SROW);

    int tid = threadIdx.x;
    int wid = tid >> 5, lane = tid & 31;

    // triangular map: blockIdx -> (ti, tj), ti <= tj. C(t) = t*(129-t)/2
    int b = blockIdx.x;
    int ti = (int)((129.0 - sqrt(129.0 * 129.0 - 8.0 * (double)b)) * 0.5);
    if (ti > 63) ti = 63;
    if (ti < 0) ti = 0;
    while (ti < 63 && (ti + 1) * (129 - (ti + 1)) / 2 <= b) ti++;
    while (ti > 0 && ti * (129 - ti) / 2 > b) ti--;
    int tj = ti + (b - ti * (129 - ti) / 2);

    // load 128x192 bf16 tiles (row-major, padded stride)
    const __nv_bfloat16* ga = g_ZA + (size_t)ti * 128 * 192;
    const __nv_bfloat16* gb = g_ZB + (size_t)tj * 128 * 192;
    #pragma unroll
    for (int it = 0; it < 12; it++) {
        int t = tid + it * 256;          // 0..3071, 8 bf16 each
        int r = t / 24, c = (t % 24) * 8;
        *(uint4*)&As[r * SROW + c] = *(const uint4*)(ga + r * 192 + c);
        *(uint4*)&Bs[r * SROW + c] = *(const uint4*)(gb + r * 192 + c);
    }
    __syncthreads();

    // warp grid 4(M) x 2(N): warp tile 32x64
    int mbase = (wid & 3) * 32;
    int nbase = (wid >> 2) * 64;
    int g = lane >> 2, t4 = lane & 3;

    float acc[2][8][4];
    #pragma unroll
    for (int mt = 0; mt < 2; mt++)
        #pragma unroll
        for (int nt = 0; nt < 8; nt++)
            #pragma unroll
            for (int q = 0; q < 4; q++) acc[mt][nt][q] = 0.f;

    #pragma unroll
    for (int ks = 0; ks < 12; ks++) {
        int k0 = ks * 16 + t4 * 2;
        uint32_t afr[2][4], bfr[8][2];
        #pragma unroll
        for (int mt = 0; mt < 2; mt++) {
            int r = mbase + mt * 16 + g;
            afr[mt][0] = *(const uint32_t*)&As[r * SROW + k0];
            afr[mt][1] = *(const uint32_t*)&As[(r + 8) * SROW + k0];
            afr[mt][2] = *(const uint32_t*)&As[r * SROW + k0 + 8];
            afr[mt][3] = *(const uint32_t*)&As[(r + 8) * SROW + k0 + 8];
        }
        #pragma unroll
        for (int nt = 0; nt < 8; nt++) {
            int r = nbase + nt * 8 + g;
            bfr[nt][0] = *(const uint32_t*)&Bs[r * SROW + k0];
            bfr[nt][1] = *(const uint32_t*)&Bs[r * SROW + k0 + 8];
        }
        #pragma unroll
        for (int mt = 0; mt < 2; mt++)
            #pragma unroll
            for (int nt = 0; nt < 8; nt++)
                mma_bf16(acc[mt][nt], afr[mt], bfr[nt]);
    }

    // fused softplus reduction; every C element held exactly once by one lane
    float s = 0.f;
    #pragma unroll
    for (int mt = 0; mt < 2; mt++) {
        #pragma unroll
        for (int half = 0; half < 2; half++) {   // groups of 16 -> one log each
            float prod = 1.f;
            #pragma unroll
            for (int nt = 0; nt < 8; nt++) {
                float x0 = acc[mt][nt][half * 2];
                float x1 = acc[mt][nt][half * 2 + 1];
                s += fmaxf(x0, 0.f) + fmaxf(x1, 0.f);
                prod *= (1.f + __expf(-fabsf(x0)));
                prod *= (1.f + __expf(-fabsf(x1)));
            }
            s += __logf(prod);
        }
    }

    red[tid] = s;
    __syncthreads();
    #pragma unroll
    for (int o = 128; o; o >>= 1) {
        if (tid < o) red[tid] += red[tid + o];
        __syncthreads();
    }
    if (tid == 0) {
        double w = (ti == tj) ? 1.0 : 2.0;
        atomicAdd(&g_sp_sum, w * (double)red[0]);
    }
}

// ---------------- finalize ----------------
__global__ void k_finalize(float* __restrict__ out) {
    int i = blockIdx.x * blockDim.x + threadIdx.x;
    float recon = (float)((g_edge_sum - g_sp_sum) / (double)N_NODES);
    if (i < N_NODES * OUT_FEAT) out[i] -= recon;
}

// ---------------- launch ----------------
extern "C" void kernel_launch(void* const* d_in, const int* in_sizes, int n_in,
                              void* d_out, int out_size) {
    const float* h   = (const float*)d_in[0];
    const int*   src = (const int*)d_in[1];
    const int*   dst = (const int*)d_in[2];
    const float* eps = (const float*)d_in[3];
    const float* w0  = (const float*)d_in[4];
    const float* wmu = (const float*)d_in[5];
    const float* wls = (const float*)d_in[6];
    float* out = (float*)d_out;

    static bool attr_done = false;
    if (!attr_done) {
        cudaFuncSetAttribute(k_sp_mma, cudaFuncAttributeMaxDynamicSharedMemorySize, SP_SMEM);
        attr_done = true;
    }

    k_zero<<<(N_NODES + 255) / 256, 256>>>();
    k_deg<<<E_EDGES / 256, 256>>>(src);
    k_scan_norm<<<1, 1024>>>();
    k_perm<<<E_EDGES / 256, 256>>>(src, dst);
    k_gemm1<<<N_NODES / 8, 512>>>(h, w0);
    k_gather1<<<N_NODES / 8, 256>>>();
    k_gemm2<<<N_NODES / 8, 1024>>>(wmu, wls);
    k_gather2<<<N_NODES / 8, 256>>>(eps, out);
    k_prep<<<(N_NODES * OUT_FEAT) / 256, 256>>>();
    k_edge<<<256, 256>>>(src, dst);
    k_sp_mma<<<NTILES, 256, SP_SMEM>>>();
    k_finalize<<<(N_NODES * OUT_FEAT) / 256, 256>>>(out);
}

// round 5
// speedup vs baseline: 1.9857x; 1.2681x over previous
#include <cuda_runtime.h>
#include <cuda_bf16.h>
#include <cstdint>

#define N_NODES 8192
#define IN_FEAT 128
#define OUT_FEAT 64
#define E_EDGES 131072
#define C2 128

// ---------------- device scratch ----------------
__device__ int    g_deg[N_NODES];
__device__ int    g_off[N_NODES + 1];
__device__ int    g_cursor[N_NODES];
__device__ int    g_perm[E_EDGES];
__device__ float  g_norm[N_NODES];
__device__ float  g_X0[N_NODES * OUT_FEAT];
__device__ float  g_h1n[N_NODES * OUT_FEAT];
__device__ float  g_Y[N_NODES * C2];
__device__ float  g_z[N_NODES * OUT_FEAT];
__device__ __nv_bfloat16 g_zh[N_NODES * OUT_FEAT];   // bf16 copy of z
__device__ double g_edge_sum;
__device__ double g_sp_sum;

// ---------------- init / graph prep ----------------
__global__ void k_zero() {
    int i = blockIdx.x * blockDim.x + threadIdx.x;
    if (i < N_NODES) g_deg[i] = 0;
    if (i == 0) { g_edge_sum = 0.0; g_sp_sum = 0.0; }
}
__global__ void k_deg(const int* __restrict__ src) {
    int e = blockIdx.x * blockDim.x + threadIdx.x;
    if (e < E_EDGES) atomicAdd(&g_deg[src[e]], 1);
}
__global__ void k_scan_norm() {
    __shared__ int part[1024];
    int tid = threadIdx.x;
    int base = tid * 8;
    int local[8];
    int s = 0;
    #pragma unroll
    for (int j = 0; j < 8; j++) { local[j] = s; s += g_deg[base + j]; }
    part[tid] = s;
    __syncthreads();
    for (int off = 1; off < 1024; off <<= 1) {
        int v = (tid >= off) ? part[tid - off] : 0;
        __syncthreads();
        part[tid] += v;
        __syncthreads();
    }
    int pre = (tid > 0) ? part[tid - 1] : 0;
    #pragma unroll
    for (int j = 0; j < 8; j++) {
        int o = pre + local[j];
        g_off[base + j] = o;
        g_cursor[base + j] = o;
        int d = g_deg[base + j];
        g_norm[base + j] = rsqrtf((float)(d < 1 ? 1 : d));
    }
    if (tid == 1023) g_off[N_NODES] = pre + s;
}
__global__ void k_perm(const int* __restrict__ src, const int* __restrict__ dst) {
    int e = blockIdx.x * blockDim.x + threadIdx.x;
    if (e < E_EDGES) {
        int p = atomicAdd(&g_cursor[src[e]], 1);
        g_perm[p] = dst[e];
    }
}

// ---------------- GEMM 1: X0 = (h * norm) @ w0 ----------------
__global__ void __launch_bounds__(512) k_gemm1(const float* __restrict__ h,
                                               const float* __restrict__ w0) {
    __shared__ float ws[IN_FEAT][OUT_FEAT];
    __shared__ float hs[8][IN_FEAT];
    int tid = threadIdx.x;
    int row0 = blockIdx.x * 8;
    for (int t = tid; t < IN_FEAT * OUT_FEAT; t += 512)
        ws[t >> 6][t & 63] = w0[t];
    for (int t = tid; t < 8 * IN_FEAT; t += 512) {
        int r = t >> 7, k = t & 127;
        hs[r][k] = h[(row0 + r) * IN_FEAT + k] * g_norm[row0 + r];
    }
    __syncthreads();
    int r = tid >> 6, c = tid & 63;
    float acc = 0.f;
    #pragma unroll
    for (int k = 0; k < IN_FEAT; k++) acc = fmaf(hs[r][k], ws[k][c], acc);
    g_X0[(row0 + r) * OUT_FEAT + c] = acc;
}

// ---------------- gather 1 ----------------
__global__ void k_gather1() {
    int w = (blockIdx.x * blockDim.x + threadIdx.x) >> 5;
    int lane = threadIdx.x & 31;
    if (w >= N_NODES) return;
    int beg = g_off[w], end = g_off[w + 1];
    float a0 = 0.f, a1 = 0.f;
    for (int e = beg; e < end; e++) {
        int d = g_perm[e];
        const float* xr = &g_X0[d * OUT_FEAT];
        a0 += xr[lane];
        a1 += xr[lane + 32];
    }
    float nm = g_norm[w];
    g_h1n[w * OUT_FEAT + lane]      = fmaxf(a0 * nm, 0.f) * nm;
    g_h1n[w * OUT_FEAT + lane + 32] = fmaxf(a1 * nm, 0.f) * nm;
}

// ---------------- GEMM 2: Y = h1n @ [w_mu | w_ls] ----------------
__global__ void __launch_bounds__(1024) k_gemm2(const float* __restrict__ wmu,
                                                const float* __restrict__ wls) {
    __shared__ float ws[OUT_FEAT][C2];
    __shared__ float hs[8][OUT_FEAT];
    int tid = threadIdx.x;
    int row0 = blockIdx.x * 8;
    for (int t = tid; t < OUT_FEAT * OUT_FEAT; t += 1024) {
        int k = t >> 6, c = t & 63;
        ws[k][c]      = wmu[t];
        ws[k][c + 64] = wls[t];
    }
    for (int t = tid; t < 8 * OUT_FEAT; t += 1024) {
        int r = t >> 6, k = t & 63;
        hs[r][k] = g_h1n[(row0 + r) * OUT_FEAT + k];
    }
    __syncthreads();
    int r = tid >> 7, c = tid & 127;
    float acc = 0.f;
    #pragma unroll
    for (int k = 0; k < OUT_FEAT; k++) acc = fmaf(hs[r][k], ws[k][c], acc);
    g_Y[(row0 + r) * C2 + c] = acc;
}

// ---------------- gather 2 + reparam + KL + bf16 pack ----------------
__global__ void k_gather2(const float* __restrict__ eps, float* __restrict__ out) {
    int w = (blockIdx.x * blockDim.x + threadIdx.x) >> 5;
    int lane = threadIdx.x & 31;
    if (w >= N_NODES) return;
    int beg = g_off[w], end = g_off[w + 1];
    float m0 = 0.f, m1 = 0.f, l0 = 0.f, l1 = 0.f;
    for (int e = beg; e < end; e++) {
        int d = g_perm[e];
        const float* yr = &g_Y[d * C2];
        m0 += yr[lane];      m1 += yr[lane + 32];
        l0 += yr[lane + 64]; l1 += yr[lane + 96];
    }
    float nm = g_norm[w];
    m0 *= nm; m1 *= nm; l0 *= nm; l1 *= nm;
    float s0 = __expf(l0), s1 = __expf(l1);
    float z0 = m0 + s0 * eps[w * OUT_FEAT + lane];
    float z1 = m1 + s1 * eps[w * OUT_FEAT + lane + 32];
    g_z[w * OUT_FEAT + lane]      = z0;
    g_z[w * OUT_FEAT + lane + 32] = z1;
    g_zh[w * OUT_FEAT + lane]      = __float2bfloat16(z0);
    g_zh[w * OUT_FEAT + lane + 32] = __float2bfloat16(z1);
    out[w * OUT_FEAT + lane]      = -l0 + 0.5f * (s0 * s0 + m0 * m0 - 1.f);
    out[w * OUT_FEAT + lane + 32] = -l1 + 0.5f * (s1 * s1 + m1 * m1 - 1.f);
}

// ---------------- edge term (fp32, exact) ----------------
__global__ void k_edge(const int* __restrict__ src, const int* __restrict__ dst) {
    int gw = (blockIdx.x * blockDim.x + threadIdx.x) >> 5;
    int lane = threadIdx.x & 31;
    int nwarps = (gridDim.x * blockDim.x) >> 5;
    float acc = 0.f;
    for (int e = gw; e < E_EDGES; e += nwarps) {
        int s = src[e], d = dst[e];
        acc += g_z[s * OUT_FEAT + lane] * g_z[d * OUT_FEAT + lane]
             + g_z[s * OUT_FEAT + lane + 32] * g_z[d * OUT_FEAT + lane + 32];
    }
    #pragma unroll
    for (int o = 16; o; o >>= 1) acc += __shfl_xor_sync(0xffffffffu, acc, o);
    __shared__ float red[8];
    if (lane == 0) red[threadIdx.x >> 5] = acc;
    __syncthreads();
    if (threadIdx.x == 0) {
        float s = 0.f;
        #pragma unroll
        for (int i = 0; i < 8; i++) s += red[i];
        atomicAdd(&g_edge_sum, (double)s);
    }
}

// ---------------- dominant kernel: HMMA tiles of softplus(z zT), pure bf16 K=64 ----------------
#define NTILES 2080
#define SROW 72   // bf16 stride: 36 words ≡ 4 mod 32 → conflict-free fragment loads

__device__ __forceinline__ void mma_bf16(float* c, const uint32_t* a, const uint32_t* b) {
    asm volatile(
        "mma.sync.aligned.m16n8k16.row.col.f32.bf16.bf16.f32 "
        "{%0,%1,%2,%3}, {%4,%5,%6,%7}, {%8,%9}, {%0,%1,%2,%3};"
        : "+f"(c[0]), "+f"(c[1]), "+f"(c[2]), "+f"(c[3])
        : "r"(a[0]), "r"(a[1]), "r"(a[2]), "r"(a[3]), "r"(b[0]), "r"(b[1]));
}

__global__ void __launch_bounds__(256, 2) k_sp_mma() {
    __shared__ __nv_bfloat16 As[128 * SROW];
    __shared__ __nv_bfloat16 Bs[128 * SROW];
    __shared__ float red[256];

    int tid = threadIdx.x;
    int wid = tid >> 5, lane = tid & 31;

    // triangular map: blockIdx -> (ti, tj), ti <= tj
    int b = blockIdx.x;
    int ti = (int)((129.0 - sqrt(129.0 * 129.0 - 8.0 * (double)b)) * 0.5);
    if (ti > 63) ti = 63;
    if (ti < 0) ti = 0;
    while (ti < 63 && (ti + 1) * (129 - (ti + 1)) / 2 <= b) ti++;
    while (ti > 0 && ti * (129 - ti) / 2 > b) ti--;
    int tj = ti + (b - ti * (129 - ti) / 2);

    // load 128x64 bf16 tiles (same source array; row.col mma -> z z^T)
    const __nv_bfloat16* ga = g_zh + (size_t)ti * 128 * 64;
    const __nv_bfloat16* gb = g_zh + (size_t)tj * 128 * 64;
    #pragma unroll
    for (int it = 0; it < 4; it++) {
        int t = tid + it * 256;          // 0..1023, 8 bf16 each
        int r = t >> 3, c = (t & 7) * 8;
        *(uint4*)&As[r * SROW + c] = *(const uint4*)(ga + r * 64 + c);
        *(uint4*)&Bs[r * SROW + c] = *(const uint4*)(gb + r * 64 + c);
    }
    __syncthreads();

    // warp grid 4(M) x 2(N): warp tile 32x64
    int mbase = (wid & 3) * 32;
    int nbase = (wid >> 2) * 64;
    int g = lane >> 2, t4 = lane & 3;

    float acc[2][8][4];
    #pragma unroll
    for (int mt = 0; mt < 2; mt++)
        #pragma unroll
        for (int nt = 0; nt < 8; nt++)
            #pragma unroll
            for (int q = 0; q < 4; q++) acc[mt][nt][q] = 0.f;

    #pragma unroll
    for (int ks = 0; ks < 4; ks++) {
        int k0 = ks * 16 + t4 * 2;
        uint32_t afr[2][4], bfr[8][2];
        #pragma unroll
        for (int mt = 0; mt < 2; mt++) {
            int r = mbase + mt * 16 + g;
            afr[mt][0] = *(const uint32_t*)&As[r * SROW + k0];
            afr[mt][1] = *(const uint32_t*)&As[(r + 8) * SROW + k0];
            afr[mt][2] = *(const uint32_t*)&As[r * SROW + k0 + 8];
            afr[mt][3] = *(const uint32_t*)&As[(r + 8) * SROW + k0 + 8];
        }
        #pragma unroll
        for (int nt = 0; nt < 8; nt++) {
            int r = nbase + nt * 8 + g;
            bfr[nt][0] = *(const uint32_t*)&Bs[r * SROW + k0];
            bfr[nt][1] = *(const uint32_t*)&Bs[r * SROW + k0 + 8];
        }
        #pragma unroll
        for (int mt = 0; mt < 2; mt++)
            #pragma unroll
            for (int nt = 0; nt < 8; nt++)
                mma_bf16(acc[mt][nt], afr[mt], bfr[nt]);
    }

    // fused softplus reduction
    float s = 0.f;
    #pragma unroll
    for (int mt = 0; mt < 2; mt++) {
        #pragma unroll
        for (int half = 0; half < 2; half++) {
            float prod = 1.f;
            #pragma unroll
            for (int nt = 0; nt < 8; nt++) {
                float x0 = acc[mt][nt][half * 2];
                float x1 = acc[mt][nt][half * 2 + 1];
                s += fmaxf(x0, 0.f) + fmaxf(x1, 0.f);
                prod *= (1.f + __expf(-fabsf(x0)));
                prod *= (1.f + __expf(-fabsf(x1)));
            }
            s += __logf(prod);
        }
    }

    red[tid] = s;
    __syncthreads();
    #pragma unroll
    for (int o = 128; o; o >>= 1) {
        if (tid < o) red[tid] += red[tid + o];
        __syncthreads();
    }
    if (tid == 0) {
        double w = (ti == tj) ? 1.0 : 2.0;
        atomicAdd(&g_sp_sum, w * (double)red[0]);
    }
}

// ---------------- finalize ----------------
__global__ void k_finalize(float* __restrict__ out) {
    int i = blockIdx.x * blockDim.x + threadIdx.x;
    float recon = (float)((g_edge_sum - g_sp_sum) / (double)N_NODES);
    if (i < N_NODES * OUT_FEAT) out[i] -= recon;
}

// ---------------- launch ----------------
extern "C" void kernel_launch(void* const* d_in, const int* in_sizes, int n_in,
                              void* d_out, int out_size) {
    const float* h   = (const float*)d_in[0];
    const int*   src = (const int*)d_in[1];
    const int*   dst = (const int*)d_in[2];
    const float* eps = (const float*)d_in[3];
    const float* w0  = (const float*)d_in[4];
    const float* wmu = (const float*)d_in[5];
    const float* wls = (const float*)d_in[6];
    float* out = (float*)d_out;

    k_zero<<<(N_NODES + 255) / 256, 256>>>();
    k_deg<<<E_EDGES / 256, 256>>>(src);
    k_scan_norm<<<1, 1024>>>();
    k_perm<<<E_EDGES / 256, 256>>>(src, dst);
    k_gemm1<<<N_NODES / 8, 512>>>(h, w0);
    k_gather1<<<N_NODES / 8, 256>>>();
    k_gemm2<<<N_NODES / 8, 1024>>>(wmu, wls);
    k_gather2<<<N_NODES / 8, 256>>>(eps, out);
    k_edge<<<256, 256>>>(src, dst);
    k_sp_mma<<<NTILES, 256>>>();
    k_finalize<<<(N_NODES * OUT_FEAT) / 256, 256>>>(out);
}

// round 6
// speedup vs baseline: 2.0206x; 1.0176x over previous
#include <cuda_runtime.h>
#include <cuda_bf16.h>
#include <cstdint>

#define N_NODES 8192
#define IN_FEAT 128
#define OUT_FEAT 64
#define E_EDGES 131072
#define C2 128

// ---------------- device scratch (self-cleaning across graph replays) ----------------
__device__ int    g_deg[N_NODES];          // zero-init; k_scan_norm re-zeroes after use
__device__ int    g_off[N_NODES + 1];
__device__ int    g_cursor[N_NODES];
__device__ int    g_perm[E_EDGES];
__device__ float  g_norm[N_NODES];
__device__ float  g_X0[N_NODES * OUT_FEAT];
__device__ float  g_h1n[N_NODES * OUT_FEAT];
__device__ float  g_Y[N_NODES * C2];
__device__ float  g_z[N_NODES * OUT_FEAT];
__device__ __nv_bfloat16 g_zh[N_NODES * OUT_FEAT];
__device__ double g_edge_sum;              // zero-init; k_deg re-zeroes each run
__device__ double g_sp_sum;

// ---------------- 1) degree count (+ reset global sums for this run) ----------------
__global__ void k_deg(const int* __restrict__ src) {
    int e = blockIdx.x * blockDim.x + threadIdx.x;
    if (e == 0) { g_edge_sum = 0.0; g_sp_sum = 0.0; }
    if (e < E_EDGES) atomicAdd(&g_deg[src[e]], 1);
}

// ---------------- 2) scan + norm (+ self-clean g_deg) ----------------
__global__ void k_scan_norm() {
    __shared__ int part[1024];
    int tid = threadIdx.x;
    int base = tid * 8;
    int local[8], dv[8];
    int s = 0;
    #pragma unroll
    for (int j = 0; j < 8; j++) {
        dv[j] = g_deg[base + j];
        local[j] = s;
        s += dv[j];
        g_deg[base + j] = 0;               // reset for next replay
    }
    part[tid] = s;
    __syncthreads();
    for (int off = 1; off < 1024; off <<= 1) {
        int v = (tid >= off) ? part[tid - off] : 0;
        __syncthreads();
        part[tid] += v;
        __syncthreads();
    }
    int pre = (tid > 0) ? part[tid - 1] : 0;
    #pragma unroll
    for (int j = 0; j < 8; j++) {
        int o = pre + local[j];
        g_off[base + j] = o;
        g_cursor[base + j] = o;
        g_norm[base + j] = rsqrtf((float)(dv[j] < 1 ? 1 : dv[j]));
    }
    if (tid == 1023) g_off[N_NODES] = pre + s;
}

// ---------------- 3) fused: perm scatter + GEMM1 (X0 = h @ w0, norm deferred) ----------------
// blocks [0,1024): gemm1 (8 rows each); blocks [1024,1280): perm (512 edges each)
__global__ void __launch_bounds__(512) k_perm_gemm1(const int* __restrict__ src,
                                                    const int* __restrict__ dst,
                                                    const float* __restrict__ h,
                                                    const float* __restrict__ w0) {
    int tid = threadIdx.x;
    if (blockIdx.x < 1024) {
        __shared__ float ws[IN_FEAT][OUT_FEAT];
        __shared__ float hs[8][IN_FEAT];
        int row0 = blockIdx.x * 8;
        for (int t = tid; t < IN_FEAT * OUT_FEAT; t += 512)
            ws[t >> 6][t & 63] = w0[t];
        for (int t = tid; t < 8 * IN_FEAT; t += 512) {
            int r = t >> 7, k = t & 127;
            hs[r][k] = h[(row0 + r) * IN_FEAT + k];
        }
        __syncthreads();
        int r = tid >> 6, c = tid & 63;
        float acc = 0.f;
        #pragma unroll
        for (int k = 0; k < IN_FEAT; k++) acc = fmaf(hs[r][k], ws[k][c], acc);
        g_X0[(row0 + r) * OUT_FEAT + c] = acc;
    } else {
        int e = (blockIdx.x - 1024) * 512 + tid;
        if (e < E_EDGES) {
            int p = atomicAdd(&g_cursor[src[e]], 1);
            g_perm[p] = dst[e];
        }
    }
}

// ---------------- 4) gather 1: h1n = relu(norm_w * sum norm_d * X0[d]) * norm_w ----------------
__global__ void k_gather1() {
    int w = (blockIdx.x * blockDim.x + threadIdx.x) >> 5;
    int lane = threadIdx.x & 31;
    if (w >= N_NODES) return;
    int beg = g_off[w], end = g_off[w + 1];
    float a0 = 0.f, a1 = 0.f;
    int e = beg;
    for (; e + 4 <= end; e += 4) {
        int d0 = g_perm[e], d1 = g_perm[e + 1], d2 = g_perm[e + 2], d3 = g_perm[e + 3];
        float n0 = g_norm[d0], n1 = g_norm[d1], n2 = g_norm[d2], n3 = g_norm[d3];
        float x00 = g_X0[d0 * OUT_FEAT + lane],      x01 = g_X0[d0 * OUT_FEAT + lane + 32];
        float x10 = g_X0[d1 * OUT_FEAT + lane],      x11 = g_X0[d1 * OUT_FEAT + lane + 32];
        float x20 = g_X0[d2 * OUT_FEAT + lane],      x21 = g_X0[d2 * OUT_FEAT + lane + 32];
        float x30 = g_X0[d3 * OUT_FEAT + lane],      x31 = g_X0[d3 * OUT_FEAT + lane + 32];
        a0 += n0 * x00 + n1 * x10 + n2 * x20 + n3 * x30;
        a1 += n0 * x01 + n1 * x11 + n2 * x21 + n3 * x31;
    }
    for (; e < end; e++) {
        int d = g_perm[e];
        float nd = g_norm[d];
        a0 += nd * g_X0[d * OUT_FEAT + lane];
        a1 += nd * g_X0[d * OUT_FEAT + lane + 32];
    }
    float nm = g_norm[w];
    g_h1n[w * OUT_FEAT + lane]      = fmaxf(a0 * nm, 0.f) * nm;
    g_h1n[w * OUT_FEAT + lane + 32] = fmaxf(a1 * nm, 0.f) * nm;
}

// ---------------- 5) GEMM 2: Y = h1n @ [w_mu | w_ls] ----------------
__global__ void __launch_bounds__(1024) k_gemm2(const float* __restrict__ wmu,
                                                const float* __restrict__ wls) {
    __shared__ float ws[OUT_FEAT][C2];
    __shared__ float hs[8][OUT_FEAT];
    int tid = threadIdx.x;
    int row0 = blockIdx.x * 8;
    for (int t = tid; t < OUT_FEAT * OUT_FEAT; t += 1024) {
        int k = t >> 6, c = t & 63;
        ws[k][c]      = wmu[t];
        ws[k][c + 64] = wls[t];
    }
    for (int t = tid; t < 8 * OUT_FEAT; t += 1024) {
        int r = t >> 6, k = t & 63;
        hs[r][k] = g_h1n[(row0 + r) * OUT_FEAT + k];
    }
    __syncthreads();
    int r = tid >> 7, c = tid & 127;
    float acc = 0.f;
    #pragma unroll
    for (int k = 0; k < OUT_FEAT; k++) acc = fmaf(hs[r][k], ws[k][c], acc);
    g_Y[(row0 + r) * C2 + c] = acc;
}

// ---------------- 6) gather 2 + reparam + KL + bf16 pack ----------------
__global__ void k_gather2(const float* __restrict__ eps, float* __restrict__ out) {
    int w = (blockIdx.x * blockDim.x + threadIdx.x) >> 5;
    int lane = threadIdx.x & 31;
    if (w >= N_NODES) return;
    int beg = g_off[w], end = g_off[w + 1];
    float m0 = 0.f, m1 = 0.f, l0 = 0.f, l1 = 0.f;
    int e = beg;
    for (; e + 2 <= end; e += 2) {
        int d0 = g_perm[e], d1 = g_perm[e + 1];
        const float* y0 = &g_Y[d0 * C2];
        const float* y1 = &g_Y[d1 * C2];
        float a0 = y0[lane], a1 = y0[lane + 32], a2 = y0[lane + 64], a3 = y0[lane + 96];
        float b0 = y1[lane], b1 = y1[lane + 32], b2 = y1[lane + 64], b3 = y1[lane + 96];
        m0 += a0 + b0; m1 += a1 + b1; l0 += a2 + b2; l1 += a3 + b3;
    }
    for (; e < end; e++) {
        const float* yr = &g_Y[g_perm[e] * C2];
        m0 += yr[lane];      m1 += yr[lane + 32];
        l0 += yr[lane + 64]; l1 += yr[lane + 96];
    }
    float nm = g_norm[w];
    m0 *= nm; m1 *= nm; l0 *= nm; l1 *= nm;
    float s0 = __expf(l0), s1 = __expf(l1);
    float z0 = m0 + s0 * eps[w * OUT_FEAT + lane];
    float z1 = m1 + s1 * eps[w * OUT_FEAT + lane + 32];
    g_z[w * OUT_FEAT + lane]      = z0;
    g_z[w * OUT_FEAT + lane + 32] = z1;
    g_zh[w * OUT_FEAT + lane]      = __float2bfloat16(z0);
    g_zh[w * OUT_FEAT + lane + 32] = __float2bfloat16(z1);
    out[w * OUT_FEAT + lane]      = -l0 + 0.5f * (s0 * s0 + m0 * m0 - 1.f);
    out[w * OUT_FEAT + lane + 32] = -l1 + 0.5f * (s1 * s1 + m1 * m1 - 1.f);
}

// ---------------- 7) fused: edge term (blocks 0..63) + HMMA softplus tiles ----------------
#define SROW 72
#define NEDGEBLK 64
#define NTILES 2080
#define NSPGRID (NEDGEBLK + NTILES)

__device__ __forceinline__ void mma_bf16(float* c, const uint32_t* a, const uint32_t* b) {
    asm volatile(
        "mma.sync.aligned.m16n8k16.row.col.f32.bf16.bf16.f32 "
        "{%0,%1,%2,%3}, {%4,%5,%6,%7}, {%8,%9}, {%0,%1,%2,%3};"
        : "+f"(c[0]), "+f"(c[1]), "+f"(c[2]), "+f"(c[3])
        : "r"(a[0]), "r"(a[1]), "r"(a[2]), "r"(a[3]), "r"(b[0]), "r"(b[1]));
}

__global__ void __launch_bounds__(256, 2) k_sp_edge(const int* __restrict__ src,
                                                    const int* __restrict__ dst) {
    __shared__ __nv_bfloat16 As[128 * SROW];
    __shared__ __nv_bfloat16 Bs[128 * SROW];
    __shared__ float red[256];

    int tid = threadIdx.x;
    int wid = tid >> 5, lane = tid & 31;

    if (blockIdx.x < NEDGEBLK) {
        // ---- edge term: sum_e z[src].z[dst] (fp32, exact) ----
        int gw = blockIdx.x * 8 + wid;          // 512 warps total
        float acc = 0.f;
        for (int e = gw; e < E_EDGES; e += NEDGEBLK * 8) {
            int s = src[e], d = dst[e];
            acc += g_z[s * OUT_FEAT + lane] * g_z[d * OUT_FEAT + lane]
                 + g_z[s * OUT_FEAT + lane + 32] * g_z[d * OUT_FEAT + lane + 32];
        }
        #pragma unroll
        for (int o = 16; o; o >>= 1) acc += __shfl_xor_sync(0xffffffffu, acc, o);
        if (lane == 0) red[wid] = acc;
        __syncthreads();
        if (tid == 0) {
            float s = 0.f;
            #pragma unroll
            for (int i = 0; i < 8; i++) s += red[i];
            atomicAdd(&g_edge_sum, (double)s);
        }
        return;
    }

    // ---- softplus tile: triangular map over 64x64 tile grid ----
    int b = blockIdx.x - NEDGEBLK;
    int ti = (int)((129.0 - sqrt(129.0 * 129.0 - 8.0 * (double)b)) * 0.5);
    if (ti > 63) ti = 63;
    if (ti < 0) ti = 0;
    while (ti < 63 && (ti + 1) * (129 - (ti + 1)) / 2 <= b) ti++;
    while (ti > 0 && ti * (129 - ti) / 2 > b) ti--;
    int tj = ti + (b - ti * (129 - ti) / 2);

    const __nv_bfloat16* ga = g_zh + (size_t)ti * 128 * 64;
    const __nv_bfloat16* gb = g_zh + (size_t)tj * 128 * 64;
    #pragma unroll
    for (int it = 0; it < 4; it++) {
        int t = tid + it * 256;
        int r = t >> 3, c = (t & 7) * 8;
        *(uint4*)&As[r * SROW + c] = *(const uint4*)(ga + r * 64 + c);
        *(uint4*)&Bs[r * SROW + c] = *(const uint4*)(gb + r * 64 + c);
    }
    __syncthreads();

    int mbase = (wid & 3) * 32;
    int nbase = (wid >> 2) * 64;
    int g = lane >> 2, t4 = lane & 3;

    float acc[2][8][4];
    #pragma unroll
    for (int mt = 0; mt < 2; mt++)
        #pragma unroll
        for (int nt = 0; nt < 8; nt++)
            #pragma unroll
            for (int q = 0; q < 4; q++) acc[mt][nt][q] = 0.f;

    #pragma unroll
    for (int ks = 0; ks < 4; ks++) {
        int k0 = ks * 16 + t4 * 2;
        uint32_t afr[2][4], bfr[8][2];
        #pragma unroll
        for (int mt = 0; mt < 2; mt++) {
            int r = mbase + mt * 16 + g;
            afr[mt][0] = *(const uint32_t*)&As[r * SROW + k0];
            afr[mt][1] = *(const uint32_t*)&As[(r + 8) * SROW + k0];
            afr[mt][2] = *(const uint32_t*)&As[r * SROW + k0 + 8];
            afr[mt][3] = *(const uint32_t*)&As[(r + 8) * SROW + k0 + 8];
        }
        #pragma unroll
        for (int nt = 0; nt < 8; nt++) {
            int r = nbase + nt * 8 + g;
            bfr[nt][0] = *(const uint32_t*)&Bs[r * SROW + k0];
            bfr[nt][1] = *(const uint32_t*)&Bs[r * SROW + k0 + 8];
        }
        #pragma unroll
        for (int mt = 0; mt < 2; mt++)
            #pragma unroll
            for (int nt = 0; nt < 8; nt++)
                mma_bf16(acc[mt][nt], afr[mt], bfr[nt]);
    }

    float s = 0.f;
    #pragma unroll
    for (int mt = 0; mt < 2; mt++) {
        #pragma unroll
        for (int half = 0; half < 2; half++) {
            float prod = 1.f;
            #pragma unroll
            for (int nt = 0; nt < 8; nt++) {
                float x0 = acc[mt][nt][half * 2];
                float x1 = acc[mt][nt][half * 2 + 1];
                s += fmaxf(x0, 0.f) + fmaxf(x1, 0.f);
                prod *= (1.f + __expf(-fabsf(x0)));
                prod *= (1.f + __expf(-fabsf(x1)));
            }
            s += __logf(prod);
        }
    }

    red[tid] = s;
    __syncthreads();
    #pragma unroll
    for (int o = 128; o; o >>= 1) {
        if (tid < o) red[tid] += red[tid + o];
        __syncthreads();
    }
    if (tid == 0) {
        double w = (ti == tj) ? 1.0 : 2.0;
        atomicAdd(&g_sp_sum, w * (double)red[0]);
    }
}

// ---------------- 8) finalize ----------------
__global__ void k_finalize(float* __restrict__ out) {
    int i = blockIdx.x * blockDim.x + threadIdx.x;
    float recon = (float)((g_edge_sum - g_sp_sum) / (double)N_NODES);
    if (i < N_NODES * OUT_FEAT) out[i] -= recon;
}

// ---------------- launch ----------------
extern "C" void kernel_launch(void* const* d_in, const int* in_sizes, int n_in,
                              void* d_out, int out_size) {
    const float* h   = (const float*)d_in[0];
    const int*   src = (const int*)d_in[1];
    const int*   dst = (const int*)d_in[2];
    const float* eps = (const float*)d_in[3];
    const float* w0  = (const float*)d_in[4];
    const float* wmu = (const float*)d_in[5];
    const float* wls = (const float*)d_in[6];
    float* out = (float*)d_out;

    k_deg<<<E_EDGES / 256, 256>>>(src);
    k_scan_norm<<<1, 1024>>>();
    k_perm_gemm1<<<1280, 512>>>(src, dst, h, w0);
    k_gather1<<<N_NODES / 8, 256>>>();
    k_gemm2<<<N_NODES / 8, 1024>>>(wmu, wls);
    k_gather2<<<N_NODES / 8, 256>>>(eps, out);
    k_sp_edge<<<NSPGRID, 256>>>(src, dst);
    k_finalize<<<(N_NODES * OUT_FEAT) / 256, 256>>>(out);
}